// round 11
// baseline (speedup 1.0000x reference)
#include <cuda_runtime.h>
#include <cuda_bf16.h>
#include <math.h>
#include <stdint.h>

#define NN 100000
#define DD 128
#define NE 800000
#define BMT 32
#define NTILES (NN / BMT)               // 3125, exact
#define KPAD 264
#define NBLK 98                         // ceil(NN/1024)
#define GEMM_GRID 148

// ---------------------------------------------------------------------------
__device__ float g_h[NN * DD];
__device__ float g_sum[DD];
__device__ float g_sumsq[DD];
__device__ int   g_cnt[NN];
__device__ int   g_ptr[NN + 1];
__device__ int   g_cur[NN];
__device__ int   g_csrc[NE];
__device__ int   g_bsum[NBLK];

// ---------------------------------------------------------------------------
__device__ __forceinline__ uint32_t smem_to_u32(const void* p) {
    uint32_t a;
    asm("{ .reg .u64 t; cvta.to.shared.u64 t, %1; cvt.u32.u64 %0, t; }"
        : "=r"(a) : "l"(p));
    return a;
}
#define LDSM_X4(r, addr) \
    asm volatile("ldmatrix.sync.aligned.m8n8.x4.shared.b16 {%0,%1,%2,%3}, [%4];" \
        : "=r"((r)[0]), "=r"((r)[1]), "=r"((r)[2]), "=r"((r)[3]) : "r"(addr))
#define MMA16816(c, a, b0, b1) \
    asm volatile("mma.sync.aligned.m16n8k16.row.col.f32.bf16.bf16.f32 " \
        "{%0,%1,%2,%3}, {%4,%5,%6,%7}, {%8,%9}, {%0,%1,%2,%3};" \
        : "+f"((c)[0]), "+f"((c)[1]), "+f"((c)[2]), "+f"((c)[3]) \
        : "r"((a)[0]), "r"((a)[1]), "r"((a)[2]), "r"((a)[3]), "r"(b0), "r"(b1))
#define BAR_SYNC(id)   asm volatile("bar.sync %0, 512;"   :: "r"(id) : "memory")
#define BAR_ARRIVE(id) asm volatile("bar.arrive %0, 512;" :: "r"(id) : "memory")

// ---------------------------------------------------------------------------
__global__ void k_count_stats(const float* __restrict__ feat,
                              const int* __restrict__ dst) {
    int tid = threadIdx.x;
    if (blockIdx.x < 512) {
        int d = tid & 127;
        int half = tid >> 7;
        float s = 0.f, s2 = 0.f;
        for (int r = blockIdx.x * 2 + half; r < NN; r += 1024) {
            float v = feat[r * DD + d];
            s += v; s2 += v * v;
        }
        atomicAdd(&g_sum[d], s);
        atomicAdd(&g_sumsq[d], s2);
    } else {
        int i = (blockIdx.x - 512) * 256 + tid;
        if (i < NE) atomicAdd(&g_cnt[dst[i]], 1);
    }
}

__global__ void k_scan1() {
    __shared__ int ws[32];
    int tid = threadIdx.x;
    int lane = tid & 31;
    int wid = tid >> 5;
    int i = blockIdx.x * 1024 + tid;
    int v = (i < NN) ? g_cnt[i] : 0;
    if (i < NN) g_cnt[i] = 0;
    int x = v;
#pragma unroll
    for (int o = 1; o < 32; o <<= 1) {
        int t = __shfl_up_sync(0xFFFFFFFFu, x, o);
        if (lane >= o) x += t;
    }
    if (lane == 31) ws[wid] = x;
    __syncthreads();
    if (wid == 0) {
        int y = ws[lane];
#pragma unroll
        for (int o = 1; o < 32; o <<= 1) {
            int t = __shfl_up_sync(0xFFFFFFFFu, y, o);
            if (lane >= o) y += t;
        }
        ws[lane] = y;
    }
    __syncthreads();
    int incl = x + (wid > 0 ? ws[wid - 1] : 0);
    if (i < NN) g_ptr[i] = incl - v;
    if (tid == 1023) g_bsum[blockIdx.x] = incl;
}

__global__ void k_scan23() {
    __shared__ int ws[4];
    __shared__ int sb[NBLK];
    int tid = threadIdx.x;
    int lane = tid & 31;
    int w = tid >> 5;
    int x = 0, v = 0;
    if (tid < 128) {
        v = (tid < NBLK) ? g_bsum[tid] : 0;
        x = v;
#pragma unroll
        for (int o = 1; o < 32; o <<= 1) {
            int t = __shfl_up_sync(0xFFFFFFFFu, x, o);
            if (lane >= o) x += t;
        }
        if (lane == 31) ws[w] = x;
    }
    __syncthreads();
    if (tid < 128) {
        int off = 0;
        for (int k = 0; k < w; k++) off += ws[k];
        if (tid < NBLK) sb[tid] = x + off - v;
    }
    __syncthreads();
    int i = blockIdx.x * blockDim.x + tid;
    if (i < NN) {
        int p = g_ptr[i] + sb[i >> 10];
        g_ptr[i] = p;
        g_cur[i] = p;
    }
    if (i == 0) g_ptr[NN] = NE;
}

__global__ void k_norm_scatter(const float* __restrict__ feat,
                               const float* __restrict__ gamma,
                               const float* __restrict__ beta,
                               const int* __restrict__ src,
                               const int* __restrict__ dst) {
    int tid = threadIdx.x;
    if (blockIdx.x < 1024) {
        int d = tid & 127;
        int half = tid >> 7;
        const float invN = 1.f / (float)NN;
        float mean = g_sum[d] * invN;
        float var  = fmaxf(g_sumsq[d] * invN - mean * mean, 0.f);
        float isg  = rsqrtf(var + 1e-5f) * gamma[d];
        float be   = beta[d];
        for (int r = blockIdx.x * 2 + half; r < NN; r += 2048)
            g_h[r * DD + d] = (feat[r * DD + d] - mean) * isg + be;
    } else {
        int i = (blockIdx.x - 1024) * 256 + tid;
        if (i < NE) {
            int pos = atomicAdd(&g_cur[dst[i]], 1);
            g_csrc[pos] = src[i];
        }
    }
}

// ---------------------------------------------------------------------------
// Warp-specialized bf16x3 GEMM: warps 0-7 produce A tiles (CSR gather + h
// load + bf16 split) into a double buffer; warps 8-15 consume (MMA+GELU).
// Named barriers: FULL[buf]=1+buf, EMPTY[buf]=3+buf (arrive/sync, 512 total).
__device__ __forceinline__ float gelu_exact(float x) {
    return 0.5f * x * (1.f + erff(x * 0.70710678118654752f));
}
__device__ __forceinline__ uint32_t pack_bf16x2(__nv_bfloat16 lo, __nv_bfloat16 hi) {
    __nv_bfloat162 p(lo, hi);
    return *reinterpret_cast<uint32_t*>(&p);
}

#define APLANE  (BMT * KPAD * 2)            // 16896 B
#define SM_BHI  0
#define SM_BLO  (SM_BHI + DD * KPAD * 2)    // 67584
#define SM_AB   (SM_BLO + DD * KPAD * 2)    // 135168; buf b at SM_AB + b*2*APLANE
#define SM_BIAS (SM_AB + 4 * APLANE)        // 202752
#define SM_TOT  (SM_BIAS + 512)             // 203264

__global__ void __launch_bounds__(512, 1)
k_gemm_mma(const float* __restrict__ Wself,
           const float* __restrict__ Wneigh,
           const float* __restrict__ bias,
           float* __restrict__ out) {
    extern __shared__ char smem[];
    const uint32_t smem_base = smem_to_u32(smem);
    const int tid  = threadIdx.x;
    const int wid  = tid >> 5;
    const int lane = tid & 31;

    if (blockIdx.x == 0 && tid < DD) { g_sum[tid] = 0.f; g_sumsq[tid] = 0.f; }

    // ---- stage B once (all 512 threads): transpose, +I, bf16 hi/lo
    for (int i = 0; i < 16; i++) {
        int e = tid + i * 512;
        int k = e >> 5;
        int c4 = e & 31;
        const float4* wr = (k < DD)
            ? reinterpret_cast<const float4*>(Wself  + (size_t)k * DD)
            : reinterpret_cast<const float4*>(Wneigh + (size_t)(k - DD) * DD);
        float4 w = wr[c4];
        float wv[4] = {w.x, w.y, w.z, w.w};
#pragma unroll
        for (int j = 0; j < 4; j++) {
            int n = c4 * 4 + j;
            float vv = wv[j] + ((k < DD && n == k) ? 1.0f : 0.0f);
            __nv_bfloat16 hi = __float2bfloat16(vv);
            __nv_bfloat16 lo = __float2bfloat16(vv - __bfloat162float(hi));
            uint32_t off = ((uint32_t)n * KPAD + (uint32_t)k) * 2u;
            *reinterpret_cast<__nv_bfloat16*>(smem + SM_BHI + off) = hi;
            *reinterpret_cast<__nv_bfloat16*>(smem + SM_BLO + off) = lo;
        }
    }
    if (tid < DD) *reinterpret_cast<float*>(smem + SM_BIAS + tid * 4) = bias[tid];
    __syncthreads();

    if (wid < 8) {
        // =================== PRODUCER warps 0-7 ===========================
        const int pw = wid;                 // gather rows pw*4 .. pw*4+3
        int it = 0;
        for (int tile = blockIdx.x; tile < NTILES; tile += GEMM_GRID, it++) {
            const int row0 = tile * BMT;
            const int buf = it & 1;
            const uint32_t abase = SM_AB + (uint32_t)buf * 2 * APLANE;

            // gather 4 rows into registers (4 interleaved chains)
            float4 acc[4];
            int dg[4], bj[4], ej[4];
#pragma unroll
            for (int j = 0; j < 4; j++) {
                int gr = row0 + pw * 4 + j;
                bj[j] = g_ptr[gr];
                ej[j] = g_ptr[gr + 1];
                dg[j] = ej[j] - bj[j];
                acc[j] = make_float4(0.f, 0.f, 0.f, 0.f);
            }
            while ((bj[0] < ej[0]) | (bj[1] < ej[1]) |
                   (bj[2] < ej[2]) | (bj[3] < ej[3])) {
#pragma unroll
                for (int j = 0; j < 4; j++) {
                    if (bj[j] < ej[j]) {
                        int s = g_csrc[bj[j]++];
                        float4 t = reinterpret_cast<const float4*>(
                                       g_h + (size_t)s * DD)[lane];
                        acc[j].x += t.x; acc[j].y += t.y;
                        acc[j].z += t.z; acc[j].w += t.w;
                    }
                }
            }
            // load h rows (4 float4 per producer thread)
            float4 v[4];
#pragma unroll
            for (int i = 0; i < 4; i++) {
                int e = tid + i * 256;      // 0..1023
                int r  = e >> 5;            // 0..31
                int c4 = e & 31;
                v[i] = reinterpret_cast<const float4*>(
                           g_h + (size_t)(row0 + r) * DD)[c4];
            }

            if (it >= 2) BAR_SYNC(3 + buf);     // wait consumers released buf

            // store h half (cols 0..127)
#pragma unroll
            for (int i = 0; i < 4; i++) {
                int e = tid + i * 256;
                int r  = e >> 5;
                int c4 = e & 31;
                float x[4] = {v[i].x, v[i].y, v[i].z, v[i].w};
                __nv_bfloat16 h[4], l[4];
#pragma unroll
                for (int j = 0; j < 4; j++) {
                    h[j] = __float2bfloat16(x[j]);
                    l[j] = __float2bfloat16(x[j] - __bfloat162float(h[j]));
                }
                uint32_t boff = abase + ((uint32_t)r * KPAD + (uint32_t)c4 * 4) * 2u;
                *reinterpret_cast<uint2*>(smem + boff) =
                    make_uint2(pack_bf16x2(h[0], h[1]), pack_bf16x2(h[2], h[3]));
                *reinterpret_cast<uint2*>(smem + boff + APLANE) =
                    make_uint2(pack_bf16x2(l[0], l[1]), pack_bf16x2(l[2], l[3]));
            }
            // store gathered means (cols 128..255)
#pragma unroll
            for (int j = 0; j < 4; j++) {
                float iv = 1.f / fmaxf((float)dg[j], 1.f);
                float x[4] = {acc[j].x * iv, acc[j].y * iv,
                              acc[j].z * iv, acc[j].w * iv};
                __nv_bfloat16 h[4], l[4];
#pragma unroll
                for (int q = 0; q < 4; q++) {
                    h[q] = __float2bfloat16(x[q]);
                    l[q] = __float2bfloat16(x[q] - __bfloat162float(h[q]));
                }
                uint32_t boff = abase + ((uint32_t)(pw * 4 + j) * KPAD + 128u
                                         + (uint32_t)lane * 4u) * 2u;
                *reinterpret_cast<uint2*>(smem + boff) =
                    make_uint2(pack_bf16x2(h[0], h[1]), pack_bf16x2(h[2], h[3]));
                *reinterpret_cast<uint2*>(smem + boff + APLANE) =
                    make_uint2(pack_bf16x2(l[0], l[1]), pack_bf16x2(l[2], l[3]));
            }
            BAR_ARRIVE(1 + buf);                // buf is FULL
        }
    } else {
        // =================== CONSUMER warps 8-15 ==========================
        const int cw  = wid - 8;
        const int wr2 = cw >> 2;            // rows wr2*16 .. +15
        const int wc  = cw & 3;             // cols wc*32 .. +31
        const int a_row_l = lane & 15;
        const int a_k_l   = (lane >> 4) << 3;
        const int b_n_l   = ((lane >> 4) << 3) + (lane & 7);
        const int b_k_l   = ((lane >> 3) & 1) << 3;
        const float* bias_s = reinterpret_cast<const float*>(smem + SM_BIAS);

        int it = 0;
        for (int tile = blockIdx.x; tile < NTILES; tile += GEMM_GRID, it++) {
            const int row0 = tile * BMT;
            const int buf = it & 1;
            const uint32_t a_hi_base = smem_base + SM_AB + (uint32_t)buf * 2 * APLANE;
            const uint32_t a_lo_base = a_hi_base + APLANE;

            BAR_SYNC(1 + buf);                  // wait buf FULL

            float c[4][4];
#pragma unroll
            for (int nt = 0; nt < 4; nt++)
#pragma unroll
                for (int q = 0; q < 4; q++) c[nt][q] = 0.f;

#pragma unroll 4
            for (int ks = 0; ks < 16; ks++) {
                const int k0 = ks * 16;
                uint32_t a_hi[4], a_lo[4], b_hi[2][4], b_lo[2][4];
                {
                    uint32_t ao = (uint32_t)((wr2 * 16 + a_row_l) * KPAD
                                             + k0 + a_k_l) * 2u;
                    LDSM_X4(a_hi, a_hi_base + ao);
                    LDSM_X4(a_lo, a_lo_base + ao);
                }
#pragma unroll
                for (int g = 0; g < 2; g++) {
                    uint32_t bo = (uint32_t)((wc * 32 + g * 16 + b_n_l) * KPAD
                                             + k0 + b_k_l) * 2u;
                    LDSM_X4(b_hi[g], smem_base + SM_BHI + bo);
                    LDSM_X4(b_lo[g], smem_base + SM_BLO + bo);
                }
#pragma unroll
                for (int nt = 0; nt < 4; nt++) {
                    int g = nt >> 1, s = (nt & 1) * 2;
                    MMA16816(c[nt], a_hi, b_hi[g][s], b_hi[g][s + 1]);
                }
#pragma unroll
                for (int nt = 0; nt < 4; nt++) {
                    int g = nt >> 1, s = (nt & 1) * 2;
                    MMA16816(c[nt], a_hi, b_lo[g][s], b_lo[g][s + 1]);
                }
#pragma unroll
                for (int nt = 0; nt < 4; nt++) {
                    int g = nt >> 1, s = (nt & 1) * 2;
                    MMA16816(c[nt], a_lo, b_hi[g][s], b_hi[g][s + 1]);
                }
            }
            BAR_ARRIVE(3 + buf);                // buf is EMPTY (reads done)

            // epilogue: bias + exact GELU + direct stores (overlaps producer)
            int rbase = row0 + wr2 * 16 + (lane >> 2);
#pragma unroll
            for (int nt = 0; nt < 4; nt++) {
                int col = wc * 32 + nt * 8 + 2 * (lane & 3);
                float b0 = bias_s[col], b1 = bias_s[col + 1];
                float2 o0 = make_float2(gelu_exact(c[nt][0] + b0),
                                        gelu_exact(c[nt][1] + b1));
                *reinterpret_cast<float2*>(out + (size_t)rbase * DD + col) = o0;
                float2 o1 = make_float2(gelu_exact(c[nt][2] + b0),
                                        gelu_exact(c[nt][3] + b1));
                *reinterpret_cast<float2*>(out + (size_t)(rbase + 8) * DD + col) = o1;
            }
        }
    }
}

// ---------------------------------------------------------------------------
extern "C" void kernel_launch(void* const* d_in, const int* in_sizes, int n_in,
                              void* d_out, int out_size) {
    const float* features = (const float*)d_in[0];
    const int*   src      = (const int*)d_in[1];
    const int*   dst      = (const int*)d_in[2];
    const float* gamma    = (const float*)d_in[3];
    const float* beta     = (const float*)d_in[4];
    const float* W_self   = (const float*)d_in[5];
    const float* W_neigh  = (const float*)d_in[6];
    const float* b        = (const float*)d_in[7];
    float* out = (float*)d_out;

    cudaFuncSetAttribute(k_gemm_mma, cudaFuncAttributeMaxDynamicSharedMemorySize, SM_TOT);

    k_count_stats<<<512 + (NE + 255) / 256, 256>>>(features, dst);
    k_scan1<<<NBLK, 1024>>>();
    k_scan23<<<(NN + 255) / 256, 256>>>();
    k_norm_scatter<<<1024 + (NE + 255) / 256, 256>>>(features, gamma, beta, src, dst);
    k_gemm_mma<<<GEMM_GRID, 512, SM_TOT>>>(W_self, W_neigh, b, out);
}

// round 12
// speedup vs baseline: 1.2186x; 1.2186x over previous
#include <cuda_runtime.h>
#include <cuda_bf16.h>
#include <math.h>
#include <stdint.h>

#define NN 100000
#define DD 128
#define NE 800000
#define BMT 64
#define NTILES ((NN + BMT - 1) / BMT)   // 1563
#define KPAD 264
#define NBLK 98                         // ceil(NN/1024)
#define GEMM_GRID 148

// ---------------------------------------------------------------------------
__device__ float g_sum[DD];
__device__ float g_sumsq[DD];
__device__ int   g_cnt[NN];
__device__ int   g_ptr[NN + 1];
__device__ int   g_cur[NN];
__device__ int   g_csrc[NE];
__device__ int   g_bsum[NBLK];

// ---------------------------------------------------------------------------
__device__ __forceinline__ uint32_t smem_to_u32(const void* p) {
    uint32_t a;
    asm("{ .reg .u64 t; cvta.to.shared.u64 t, %1; cvt.u32.u64 %0, t; }"
        : "=r"(a) : "l"(p));
    return a;
}
#define LDSM_X4(r, addr) \
    asm volatile("ldmatrix.sync.aligned.m8n8.x4.shared.b16 {%0,%1,%2,%3}, [%4];" \
        : "=r"((r)[0]), "=r"((r)[1]), "=r"((r)[2]), "=r"((r)[3]) : "r"(addr))
#define MMA16816(c, a, b0, b1) \
    asm volatile("mma.sync.aligned.m16n8k16.row.col.f32.bf16.bf16.f32 " \
        "{%0,%1,%2,%3}, {%4,%5,%6,%7}, {%8,%9}, {%0,%1,%2,%3};" \
        : "+f"((c)[0]), "+f"((c)[1]), "+f"((c)[2]), "+f"((c)[3]) \
        : "r"((a)[0]), "r"((a)[1]), "r"((a)[2]), "r"((a)[3]), "r"(b0), "r"(b1))

// ---------------------------------------------------------------------------
// fused: blocks [0,512) column stats (float4 + block reduce); rest edge count.
__global__ void k_count_stats(const float* __restrict__ feat,
                              const int* __restrict__ dst) {
    __shared__ float rs[8 * 128];
    __shared__ float rq[8 * 128];
    int tid = threadIdx.x;
    if (blockIdx.x < 512) {
        int cg = tid & 31;                  // float4 column group
        int rg = tid >> 5;                  // 0..7
        float s[4] = {0.f, 0.f, 0.f, 0.f};
        float q[4] = {0.f, 0.f, 0.f, 0.f};
        for (int r = blockIdx.x * 8 + rg; r < NN; r += 4096) {
            float4 v = reinterpret_cast<const float4*>(feat + (size_t)r * DD)[cg];
            s[0] += v.x; q[0] += v.x * v.x;
            s[1] += v.y; q[1] += v.y * v.y;
            s[2] += v.z; q[2] += v.z * v.z;
            s[3] += v.w; q[3] += v.w * v.w;
        }
#pragma unroll
        for (int j = 0; j < 4; j++) {
            rs[rg * 128 + cg * 4 + j] = s[j];
            rq[rg * 128 + cg * 4 + j] = q[j];
        }
        __syncthreads();
        if (tid < 128) {
            float ts = 0.f, tq = 0.f;
#pragma unroll
            for (int g = 0; g < 8; g++) {
                ts += rs[g * 128 + tid];
                tq += rq[g * 128 + tid];
            }
            atomicAdd(&g_sum[tid], ts);
            atomicAdd(&g_sumsq[tid], tq);
        }
    } else {
        int i = (blockIdx.x - 512) * 256 + tid;
        if (i < NE) atomicAdd(&g_cnt[dst[i]], 1);
    }
}

// ---- shuffle scan level 1 (re-zeros g_cnt for the next graph replay) ------
__global__ void k_scan1() {
    __shared__ int ws[32];
    int tid = threadIdx.x;
    int lane = tid & 31;
    int wid = tid >> 5;
    int i = blockIdx.x * 1024 + tid;
    int v = (i < NN) ? g_cnt[i] : 0;
    if (i < NN) g_cnt[i] = 0;
    int x = v;
#pragma unroll
    for (int o = 1; o < 32; o <<= 1) {
        int t = __shfl_up_sync(0xFFFFFFFFu, x, o);
        if (lane >= o) x += t;
    }
    if (lane == 31) ws[wid] = x;
    __syncthreads();
    if (wid == 0) {
        int y = ws[lane];
#pragma unroll
        for (int o = 1; o < 32; o <<= 1) {
            int t = __shfl_up_sync(0xFFFFFFFFu, y, o);
            if (lane >= o) y += t;
        }
        ws[lane] = y;
    }
    __syncthreads();
    int incl = x + (wid > 0 ? ws[wid - 1] : 0);
    if (i < NN) g_ptr[i] = incl - v;
    if (tid == 1023) g_bsum[blockIdx.x] = incl;
}

__global__ void k_scan23() {
    __shared__ int ws[4];
    __shared__ int sb[NBLK];
    int tid = threadIdx.x;
    int lane = tid & 31;
    int w = tid >> 5;
    int x = 0, v = 0;
    if (tid < 128) {
        v = (tid < NBLK) ? g_bsum[tid] : 0;
        x = v;
#pragma unroll
        for (int o = 1; o < 32; o <<= 1) {
            int t = __shfl_up_sync(0xFFFFFFFFu, x, o);
            if (lane >= o) x += t;
        }
        if (lane == 31) ws[w] = x;
    }
    __syncthreads();
    if (tid < 128) {
        int off = 0;
        for (int k = 0; k < w; k++) off += ws[k];
        if (tid < NBLK) sb[tid] = x + off - v;
    }
    __syncthreads();
    int i = blockIdx.x * blockDim.x + tid;
    if (i < NN) {
        int p = g_ptr[i] + sb[i >> 10];
        g_ptr[i] = p;
        g_cur[i] = p;
    }
    if (i == 0) g_ptr[NN] = NE;
}

__global__ void k_scatter(const int* __restrict__ src, const int* __restrict__ dst) {
    int i = blockIdx.x * blockDim.x + threadIdx.x;
    if (i < NE) {
        int pos = atomicAdd(&g_cur[dst[i]], 1);
        g_csrc[pos] = src[i];
    }
}

// ---------------------------------------------------------------------------
// bf16x3 mma.sync GEMM with on-the-fly BatchNorm (affine folded into staging;
// gathers sum RAW features — affine commutes with the mean) and shadowed
// CSR gather (R10 structure).
__device__ __forceinline__ float gelu_exact(float x) {
    return 0.5f * x * (1.f + erff(x * 0.70710678118654752f));
}
__device__ __forceinline__ uint32_t pack_bf16x2(__nv_bfloat16 lo, __nv_bfloat16 hi) {
    __nv_bfloat162 p(lo, hi);
    return *reinterpret_cast<uint32_t*>(&p);
}

#define SM_BHI  0
#define SM_BLO  (SM_BHI + DD * KPAD * 2)    // 67584
#define SM_A    (SM_BLO + DD * KPAD * 2)    // 135168
#define SM_ALO  (SM_A + BMT * KPAD * 2)     // 168960
#define SM_BIAS (SM_ALO + BMT * KPAD * 2)   // 202752
#define SM_ISG  (SM_BIAS + 512)             // 203264
#define SM_OFF  (SM_ISG + 512)              // 203776
#define SM_TOT  (SM_OFF + 512)              // 204288

__global__ void __launch_bounds__(512, 1)
k_gemm_mma(const float* __restrict__ feat,
           const float* __restrict__ gamma,
           const float* __restrict__ beta,
           const float* __restrict__ Wself,
           const float* __restrict__ Wneigh,
           const float* __restrict__ bias,
           float* __restrict__ out) {
    extern __shared__ char smem[];
    const uint32_t smem_base = smem_to_u32(smem);
    const int tid  = threadIdx.x;
    const int wid  = tid >> 5;
    const int lane = tid & 31;

    // ---- BN affine constants from the accumulated stats
    if (tid < DD) {
        const float invN = 1.f / (float)NN;
        float mean = g_sum[tid] * invN;
        float var  = fmaxf(g_sumsq[tid] * invN - mean * mean, 0.f);
        float is   = rsqrtf(var + 1e-5f) * gamma[tid];
        reinterpret_cast<float*>(smem + SM_ISG)[tid] = is;
        reinterpret_cast<float*>(smem + SM_OFF)[tid] = beta[tid] - mean * is;
        reinterpret_cast<float*>(smem + SM_BIAS)[tid] = bias[tid];
    }

    // ---- stage B once: transpose, +I fold, bf16 hi/lo split
    for (int i = 0; i < 16; i++) {
        int e = tid + i * 512;
        int k = e >> 5;
        int c4 = e & 31;
        const float4* wr = (k < DD)
            ? reinterpret_cast<const float4*>(Wself  + (size_t)k * DD)
            : reinterpret_cast<const float4*>(Wneigh + (size_t)(k - DD) * DD);
        float4 w = wr[c4];
        float wv[4] = {w.x, w.y, w.z, w.w};
#pragma unroll
        for (int j = 0; j < 4; j++) {
            int n = c4 * 4 + j;
            float vv = wv[j] + ((k < DD && n == k) ? 1.0f : 0.0f);
            __nv_bfloat16 hi = __float2bfloat16(vv);
            __nv_bfloat16 lo = __float2bfloat16(vv - __bfloat162float(hi));
            uint32_t off = ((uint32_t)n * KPAD + (uint32_t)k) * 2u;
            *reinterpret_cast<__nv_bfloat16*>(smem + SM_BHI + off) = hi;
            *reinterpret_cast<__nv_bfloat16*>(smem + SM_BLO + off) = lo;
        }
    }

    const float* bias_s = reinterpret_cast<const float*>(smem + SM_BIAS);
    const float* isg_s  = reinterpret_cast<const float*>(smem + SM_ISG);
    const float* off_s  = reinterpret_cast<const float*>(smem + SM_OFF);
    const int wr2 = wid >> 2;
    const int wc  = wid & 3;
    const int a_row_l = lane & 15;
    const int a_k_l   = (lane >> 4) << 3;
    const int b_n_l   = ((lane >> 4) << 3) + (lane & 7);
    const int b_k_l   = ((lane >> 3) & 1) << 3;
    const int lr0 = wid * 4;                // this warp's 4 gather rows

    float4 v[4];                            // raw feat prefetch (h half)
    float4 acc[4];                          // raw neighbor sums
    int    dg[4];

    // ---- prologue: raw gather + raw h prefetch for the first tile
    int tile = blockIdx.x;
    if (tile < NTILES) {
        const int row0 = tile * BMT;
#pragma unroll
        for (int i = 0; i < 4; i++) {
            int e = tid + i * 512;
            int r  = e >> 5;
            int c4 = e & 31;
            int gr = min(row0 + r, NN - 1);
            v[i] = reinterpret_cast<const float4*>(feat + (size_t)gr * DD)[c4];
        }
        int bj[4], ej[4];
#pragma unroll
        for (int j = 0; j < 4; j++) {
            int gr = min(row0 + lr0 + j, NN - 1);
            bj[j] = g_ptr[gr];
            ej[j] = g_ptr[gr + 1];
            dg[j] = ej[j] - bj[j];
            acc[j] = make_float4(0.f, 0.f, 0.f, 0.f);
        }
        while ((bj[0] < ej[0]) | (bj[1] < ej[1]) |
               (bj[2] < ej[2]) | (bj[3] < ej[3])) {
#pragma unroll
            for (int j = 0; j < 4; j++) {
                if (bj[j] < ej[j]) {
                    int s = g_csrc[bj[j]++];
                    float4 t = reinterpret_cast<const float4*>(
                                   feat + (size_t)s * DD)[lane];
                    acc[j].x += t.x; acc[j].y += t.y;
                    acc[j].z += t.z; acc[j].w += t.w;
                }
            }
        }
    }
    __syncthreads();   // B + affine constants ready

    for (; tile < NTILES; tile += GEMM_GRID) {
        const int row0 = tile * BMT;
        const int nxt  = tile + GEMM_GRID;

        // ---- gathered sums -> normalized mean -> smem A-neigh (cols 128..255)
#pragma unroll
        for (int j = 0; j < 4; j++) {
            float iv  = (dg[j] > 0) ? 1.f / (float)dg[j] : 0.f;
            float ofm = (dg[j] > 0) ? 1.f : 0.f;
            float a4[4] = {acc[j].x, acc[j].y, acc[j].z, acc[j].w};
            __nv_bfloat16 h[4], l[4];
#pragma unroll
            for (int q = 0; q < 4; q++) {
                int col = lane * 4 + q;
                float x = a4[q] * isg_s[col] * iv + off_s[col] * ofm;
                h[q] = __float2bfloat16(x);
                l[q] = __float2bfloat16(x - __bfloat162float(h[q]));
            }
            uint32_t boff = ((uint32_t)(lr0 + j) * KPAD + 128u
                             + (uint32_t)lane * 4u) * 2u;
            *reinterpret_cast<uint2*>(smem + SM_A + boff) =
                make_uint2(pack_bf16x2(h[0], h[1]), pack_bf16x2(h[2], h[3]));
            *reinterpret_cast<uint2*>(smem + SM_ALO + boff) =
                make_uint2(pack_bf16x2(l[0], l[1]), pack_bf16x2(l[2], l[3]));
        }
        // ---- raw h regs -> normalize -> smem A (cols 0..127)
#pragma unroll
        for (int i = 0; i < 4; i++) {
            int e = tid + i * 512;
            int r  = e >> 5;
            int c4 = e & 31;
            float x4[4] = {v[i].x, v[i].y, v[i].z, v[i].w};
            __nv_bfloat16 h[4], l[4];
#pragma unroll
            for (int j = 0; j < 4; j++) {
                int col = c4 * 4 + j;
                float x = x4[j] * isg_s[col] + off_s[col];
                h[j] = __float2bfloat16(x);
                l[j] = __float2bfloat16(x - __bfloat162float(h[j]));
            }
            uint32_t boff = ((uint32_t)r * KPAD + (uint32_t)c4 * 4) * 2u;
            *reinterpret_cast<uint2*>(smem + SM_A + boff) =
                make_uint2(pack_bf16x2(h[0], h[1]), pack_bf16x2(h[2], h[3]));
            *reinterpret_cast<uint2*>(smem + SM_ALO + boff) =
                make_uint2(pack_bf16x2(l[0], l[1]), pack_bf16x2(l[2], l[3]));
        }
        __syncthreads();

        // ---- prefetch next tile's raw h half
        if (nxt < NTILES) {
            const int nrow0 = nxt * BMT;
#pragma unroll
            for (int i = 0; i < 4; i++) {
                int e = tid + i * 512;
                int r  = e >> 5;
                int c4 = e & 31;
                int gr = min(nrow0 + r, NN - 1);
                v[i] = reinterpret_cast<const float4*>(feat + (size_t)gr * DD)[c4];
            }
        }

        float c[4][4];
#pragma unroll
        for (int nt = 0; nt < 4; nt++)
#pragma unroll
            for (int q = 0; q < 4; q++) c[nt][q] = 0.f;

#pragma unroll 4
        for (int ks = 0; ks < 16; ks++) {
            const int k0 = ks * 16;
            uint32_t a_hi[4], a_lo[4], b_hi[2][4], b_lo[2][4];
            {
                uint32_t ao = (uint32_t)((wr2 * 16 + a_row_l) * KPAD
                                         + k0 + a_k_l) * 2u;
                LDSM_X4(a_hi, smem_base + SM_A + ao);
                LDSM_X4(a_lo, smem_base + SM_ALO + ao);
            }
#pragma unroll
            for (int g = 0; g < 2; g++) {
                uint32_t bo = (uint32_t)((wc * 32 + g * 16 + b_n_l) * KPAD
                                         + k0 + b_k_l) * 2u;
                LDSM_X4(b_hi[g], smem_base + SM_BHI + bo);
                LDSM_X4(b_lo[g], smem_base + SM_BLO + bo);
            }
#pragma unroll
            for (int nt = 0; nt < 4; nt++) {
                int g = nt >> 1, s = (nt & 1) * 2;
                MMA16816(c[nt], a_hi, b_hi[g][s], b_hi[g][s + 1]);
            }
#pragma unroll
            for (int nt = 0; nt < 4; nt++) {
                int g = nt >> 1, s = (nt & 1) * 2;
                MMA16816(c[nt], a_hi, b_lo[g][s], b_lo[g][s + 1]);
            }
#pragma unroll
            for (int nt = 0; nt < 4; nt++) {
                int g = nt >> 1, s = (nt & 1) * 2;
                MMA16816(c[nt], a_lo, b_hi[g][s], b_hi[g][s + 1]);
            }
        }

        // ---- SHADOWED raw gather for next tile
        if (nxt < NTILES) {
            const int nrow0 = nxt * BMT;
            int bj[4], ej[4];
#pragma unroll
            for (int j = 0; j < 4; j++) {
                int gr = min(nrow0 + lr0 + j, NN - 1);
                bj[j] = g_ptr[gr];
                ej[j] = g_ptr[gr + 1];
                dg[j] = ej[j] - bj[j];
                acc[j] = make_float4(0.f, 0.f, 0.f, 0.f);
            }
            while ((bj[0] < ej[0]) | (bj[1] < ej[1]) |
                   (bj[2] < ej[2]) | (bj[3] < ej[3])) {
#pragma unroll
                for (int j = 0; j < 4; j++) {
                    if (bj[j] < ej[j]) {
                        int s = g_csrc[bj[j]++];
                        float4 t = reinterpret_cast<const float4*>(
                                       feat + (size_t)s * DD)[lane];
                        acc[j].x += t.x; acc[j].y += t.y;
                        acc[j].z += t.z; acc[j].w += t.w;
                    }
                }
            }
        }

        // ---- epilogue: bias + exact GELU + direct fragment stores
        {
            int rbase = row0 + wr2 * 16 + (lane >> 2);
#pragma unroll
            for (int nt = 0; nt < 4; nt++) {
                int col = wc * 32 + nt * 8 + 2 * (lane & 3);
                float b0 = bias_s[col], b1 = bias_s[col + 1];
                if (rbase < NN) {
                    float2 o = make_float2(gelu_exact(c[nt][0] + b0),
                                           gelu_exact(c[nt][1] + b1));
                    *reinterpret_cast<float2*>(out + (size_t)rbase * DD + col) = o;
                }
                if (rbase + 8 < NN) {
                    float2 o = make_float2(gelu_exact(c[nt][2] + b0),
                                           gelu_exact(c[nt][3] + b1));
                    *reinterpret_cast<float2*>(out + (size_t)(rbase + 8) * DD + col) = o;
                }
            }
        }
        __syncthreads();
    }

    // re-arm stats for the next graph replay (all blocks consumed g_sum in
    // their prologue, tens of µs ago; grid is a single co-resident wave).
    if (blockIdx.x == 0 && tid < DD) { g_sum[tid] = 0.f; g_sumsq[tid] = 0.f; }
}

// ---------------------------------------------------------------------------
extern "C" void kernel_launch(void* const* d_in, const int* in_sizes, int n_in,
                              void* d_out, int out_size) {
    const float* features = (const float*)d_in[0];
    const int*   src      = (const int*)d_in[1];
    const int*   dst      = (const int*)d_in[2];
    const float* gamma    = (const float*)d_in[3];
    const float* beta     = (const float*)d_in[4];
    const float* W_self   = (const float*)d_in[5];
    const float* W_neigh  = (const float*)d_in[6];
    const float* b        = (const float*)d_in[7];
    float* out = (float*)d_out;

    cudaFuncSetAttribute(k_gemm_mma, cudaFuncAttributeMaxDynamicSharedMemorySize, SM_TOT);

    k_count_stats<<<512 + (NE + 255) / 256, 256>>>(features, dst);
    k_scan1<<<NBLK, 1024>>>();
    k_scan23<<<(NN + 255) / 256, 256>>>();
    k_scatter<<<(NE + 255) / 256, 256>>>(src, dst);
    k_gemm_mma<<<GEMM_GRID, 512, SM_TOT>>>(features, gamma, beta,
                                           W_self, W_neigh, b, out);
}